// round 7
// baseline (speedup 1.0000x reference)
#include <cuda_runtime.h>
#include <mma.h>
#include <cuda_fp16.h>
#include <cstdint>
#include <math.h>

using namespace nvcuda;

#define SEQ 8192
#define DIM 768
#define QKV (3 * DIM)   // 2304

// ---------------- scratch (static device arrays; no allocs) ----------------
__device__ __align__(128) __half g_Xh  [(size_t)SEQ * DIM];
__device__ __align__(128) __half g_Wc  [(size_t)QKV * DIM];       // packed wq|wk|wv
__device__ __align__(128) __half g_QKVh[(size_t)SEQ * QKV];       // [q | k | v] cols
__device__ __align__(128) __half g_VTh [(size_t)DIM * SEQ];
__device__ __align__(128) __half g_P   [(size_t)SEQ * SEQ];       // exp(s), unnormalized
__device__ __align__(128) float  g_Part[(size_t)3 * SEQ * DIM];   // PV split-K partials
__device__ __align__(128) float  g_invL[SEQ];

// ---------------- helpers ----------------
__device__ __forceinline__ uint32_t smem_u32(const void* p) {
    uint32_t a;
    asm("{ .reg .u64 t; cvta.to.shared.u64 t, %1; cvt.u32.u64 %0, t; }" : "=r"(a) : "l"(p));
    return a;
}
__device__ __forceinline__ void cp_async16(uint32_t dst, const void* src) {
    asm volatile("cp.async.cg.shared.global [%0], [%1], 16;" :: "r"(dst), "l"(src) : "memory");
}
#define CP_COMMIT() asm volatile("cp.async.commit_group;" ::: "memory")
#define CP_WAIT1()  asm volatile("cp.async.wait_group 1;" ::: "memory")
#define CP_WAIT0()  asm volatile("cp.async.wait_group 0;" ::: "memory")

// ---------------------------------------------------------------------------
// NT GEMM (fp16 in, fp32 acc): C[M,N] = a * A[M,K] @ B[N,K]^T
//   a = alpha if (block col start < col_limit) else 1
// BM=128, BN=256, BK=64 (128B rows). 256 threads = 8 warps (2 x 4),
// warp tile 64 x 64 (4x4 frags) -> 8 LDSM per 16 wmma. 3-stage cp.async.
// Split-K over blockIdx.z: z covers k-iters [z*splitIters, min(+splitIters, kTot)),
// output plane offset z*planeStride (floats, EPI=0 only).
// EPI: 0 = fp32 direct store, 1 = fp16 smem-staged, 2 = fp16 staged with exp()
// ---------------------------------------------------------------------------
constexpr int BM = 128, BN = 256, BK = 64, LDSA = 72;   // 72 halves = 144B stride
constexpr int WN = BN / 4, NF = WN / 16;                // 64, 4
constexpr int STG_A = BM * LDSA, STG_B = BN * LDSA;
constexpr int SM_BYTES = 3 * (STG_A + STG_B) * 2;       // 165888

template <int EPI>
__global__ __launch_bounds__(256, 1) void gemm_nt_h(
    const __half* __restrict__ A, int lda,
    const __half* __restrict__ B, int ldb,
    void* __restrict__ Cv, int ldc,
    float alpha, int col_limit,
    int kTot, int splitIters, size_t planeStride)
{
    extern __shared__ __half smh[];
    __half* As = smh;                   // 3 x STG_A
    __half* Bs = smh + 3 * STG_A;       // 3 x STG_B

    const int tid  = threadIdx.x;
    const int warp = tid >> 5;
    const int bm   = blockIdx.y * BM;
    const int bn   = blockIdx.x * BN;
    const int wm   = (warp & 1) * 64;
    const int wn   = (warp >> 1) * WN;

    const int z    = blockIdx.z;
    const int kit0 = z * splitIters;
    const int nit  = min(splitIters, kTot - kit0);

    const uint32_t sA = smem_u32(As);
    const uint32_t sB = smem_u32(Bs);

    auto load_tile = [&](int b, int it) {
        const int k0 = (kit0 + it) * BK;
        const uint32_t dA = sA + (uint32_t)(b * STG_A) * 2;
        #pragma unroll
        for (int t = 0; t < BM * 8 / 256; t++) {
            int g = tid + t * 256;
            int r = g >> 3, c = (g & 7) << 3;
            cp_async16(dA + (uint32_t)(r * LDSA + c) * 2,
                       A + (size_t)(bm + r) * lda + k0 + c);
        }
        const uint32_t dB = sB + (uint32_t)(b * STG_B) * 2;
        #pragma unroll
        for (int t = 0; t < BN * 8 / 256; t++) {
            int g = tid + t * 256;
            int r = g >> 3, c = (g & 7) << 3;
            cp_async16(dB + (uint32_t)(r * LDSA + c) * 2,
                       B + (size_t)(bn + r) * ldb + k0 + c);
        }
        CP_COMMIT();
    };

    wmma::fragment<wmma::accumulator, 16, 16, 16, float> acc[4][NF];
    #pragma unroll
    for (int mi = 0; mi < 4; mi++)
        #pragma unroll
        for (int ni = 0; ni < NF; ni++)
            wmma::fill_fragment(acc[mi][ni], 0.0f);

    load_tile(0, 0);
    load_tile(1, 1);

    for (int i = 0; i < nit; i++) {
        if (i + 1 < nit) { CP_WAIT1(); } else { CP_WAIT0(); }
        __syncthreads();
        if (i + 2 < nit) load_tile((i + 2) % 3, i + 2);

        const int s = i % 3;
        const __half* Ab = As + s * STG_A;
        const __half* Bb = Bs + s * STG_B;

        #pragma unroll
        for (int kk = 0; kk < BK; kk += 16) {
            wmma::fragment<wmma::matrix_b, 16, 16, 16, __half, wmma::col_major> bf[NF];
            #pragma unroll
            for (int ni = 0; ni < NF; ni++)
                wmma::load_matrix_sync(bf[ni], Bb + (wn + ni * 16) * LDSA + kk, LDSA);
            #pragma unroll
            for (int mi = 0; mi < 4; mi++) {
                wmma::fragment<wmma::matrix_a, 16, 16, 16, __half, wmma::row_major> af;
                wmma::load_matrix_sync(af, Ab + (wm + mi * 16) * LDSA + kk, LDSA);
                #pragma unroll
                for (int ni = 0; ni < NF; ni++)
                    wmma::mma_sync(acc[mi][ni], af, bf[ni], acc[mi][ni]);
            }
        }
    }

    const float a = (bn < col_limit) ? alpha : 1.0f;

    if constexpr (EPI == 0) {
        float* C = (float*)Cv + (size_t)z * planeStride;
        #pragma unroll
        for (int mi = 0; mi < 4; mi++) {
            #pragma unroll
            for (int ni = 0; ni < NF; ni++) {
                #pragma unroll
                for (int e = 0; e < acc[mi][ni].num_elements; e++)
                    acc[mi][ni].x[e] *= a;
                wmma::store_matrix_sync(
                    C + (size_t)(bm + wm + mi * 16) * ldc + bn + wn + ni * 16,
                    acc[mi][ni], ldc, wmma::mem_row_major);
            }
        }
    } else {
        // stage fp32 in smem, convert to half (optionally exp), coalesced store
        constexpr int LDC_S = BN + 4;                    // 260 floats
        float* Cs = (float*)smh;                         // 128*260*4 = 133120 <= 165888
        __syncthreads();
        #pragma unroll
        for (int mi = 0; mi < 4; mi++) {
            #pragma unroll
            for (int ni = 0; ni < NF; ni++) {
                #pragma unroll
                for (int e = 0; e < acc[mi][ni].num_elements; e++)
                    acc[mi][ni].x[e] *= a;
                wmma::store_matrix_sync(Cs + (wm + mi * 16) * LDC_S + wn + ni * 16,
                                        acc[mi][ni], LDC_S, wmma::mem_row_major);
            }
        }
        __syncthreads();
        __half* C = (__half*)Cv;
        #pragma unroll
        for (int t = 0; t < 32; t++) {                   // 128x256 elems, 4/thread/iter
            int g = tid + t * 256;
            int r = g >> 6, c = (g & 63) << 2;
            float4 v = *reinterpret_cast<const float4*>(Cs + r * LDC_S + c);
            if constexpr (EPI == 2) {
                v.x = __expf(v.x); v.y = __expf(v.y);
                v.z = __expf(v.z); v.w = __expf(v.w);
            }
            __half2 h0 = __floats2half2_rn(v.x, v.y);
            __half2 h1 = __floats2half2_rn(v.z, v.w);
            uint2 u;
            u.x = *reinterpret_cast<uint32_t*>(&h0);
            u.y = *reinterpret_cast<uint32_t*>(&h1);
            *reinterpret_cast<uint2*>(C + (size_t)(bm + r) * ldc + bn + c) = u;
        }
    }
}

// ---------------- fused fp32 -> fp16 conversion (x, wq, wk, wv) ----------------
__global__ void __launch_bounds__(256) f2h_all(
    const float* __restrict__ x,  const float* __restrict__ wq,
    const float* __restrict__ wk, const float* __restrict__ wv,
    __half* __restrict__ Xh, __half* __restrict__ Wc)
{
    constexpr int NX = SEQ * DIM / 4;
    constexpr int NW = DIM * DIM / 4;
    int i = blockIdx.x * 256 + threadIdx.x;
    const float* src; __half* dst; int j;
    if (i < NX)               { src = x;  dst = Xh;                 j = i; }
    else if (i < NX + NW)     { src = wq; dst = Wc;                 j = i - NX; }
    else if (i < NX + 2 * NW) { src = wk; dst = Wc + DIM * DIM;     j = i - NX - NW; }
    else if (i < NX + 3 * NW) { src = wv; dst = Wc + 2 * DIM * DIM; j = i - NX - 2 * NW; }
    else return;
    float4 v = reinterpret_cast<const float4*>(src)[j];
    __half2 h0 = __floats2half2_rn(v.x, v.y);
    __half2 h1 = __floats2half2_rn(v.z, v.w);
    uint2 u;
    u.x = *reinterpret_cast<uint32_t*>(&h0);
    u.y = *reinterpret_cast<uint32_t*>(&h1);
    reinterpret_cast<uint2*>(dst)[j] = u;
}

// ---------------- half transpose: in[SEQ][ld] (col slice) -> out[DIM][SEQ] ----------------
__global__ void __launch_bounds__(256) transpose_h(const __half* __restrict__ in, int ld,
                                                   __half* __restrict__ out)
{
    __shared__ __half t[32][34];
    const int x0 = blockIdx.x * 32;
    const int y0 = blockIdx.y * 32;
    const int tx = threadIdx.x & 31, ty = threadIdx.x >> 5;
    #pragma unroll
    for (int j = 0; j < 4; j++)
        t[ty + 8 * j][tx] = in[(size_t)(y0 + ty + 8 * j) * ld + x0 + tx];
    __syncthreads();
    #pragma unroll
    for (int j = 0; j < 4; j++)
        out[(size_t)(x0 + ty + 8 * j) * SEQ + y0 + tx] = t[tx][ty + 8 * j];
}

// ---------------- row sums of P (fp16) -> invL (fp32) ----------------
__global__ void __launch_bounds__(256) rowsum_inv(const __half* __restrict__ P,
                                                  float* __restrict__ invL)
{
    const int row = blockIdx.x;
    const uint4* p = reinterpret_cast<const uint4*>(P + (size_t)row * SEQ);
    const int t = threadIdx.x;

    float s = 0.0f;
    #pragma unroll
    for (int i = 0; i < 4; i++) {
        uint4 u = p[t + (i << 8)];
        const __half2* h = reinterpret_cast<const __half2*>(&u);
        #pragma unroll
        for (int j = 0; j < 4; j++) {
            float2 f = __half22float2(h[j]);
            s += f.x + f.y;
        }
    }
    __shared__ float red[256];
    red[t] = s; __syncthreads();
    #pragma unroll
    for (int k = 128; k > 0; k >>= 1) { if (t < k) red[t] += red[t + k]; __syncthreads(); }
    if (t == 0) invL[row] = 1.0f / red[0];
}

// ---------------- reduce split-K partials + row-normalize ----------------
__global__ void __launch_bounds__(256) reduce_norm(const float* __restrict__ part,
                                                   float* __restrict__ out,
                                                   const float* __restrict__ invL)
{
    constexpr int PLANE4 = SEQ * DIM / 4;
    int i = blockIdx.x * 256 + threadIdx.x;
    if (i < PLANE4) {
        const float s = invL[i / (DIM / 4)];
        const float4 a = reinterpret_cast<const float4*>(part)[i];
        const float4 b = reinterpret_cast<const float4*>(part)[i + PLANE4];
        const float4 c = reinterpret_cast<const float4*>(part)[i + 2 * PLANE4];
        float4 v;
        v.x = (a.x + b.x + c.x) * s;
        v.y = (a.y + b.y + c.y) * s;
        v.z = (a.z + b.z + c.z) * s;
        v.w = (a.w + b.w + c.w) * s;
        reinterpret_cast<float4*>(out)[i] = v;
    }
}

// ---------------- launch ----------------
extern "C" void kernel_launch(void* const* d_in, const int* in_sizes, int n_in,
                              void* d_out, int out_size)
{
    const float* x  = (const float*)d_in[0];
    const float* wq = (const float*)d_in[1];
    const float* wk = (const float*)d_in[2];
    const float* wv = (const float*)d_in[3];
    float* out = (float*)d_out;

    __half *Xh, *Wc, *QKVh, *VTh, *P;
    float *Part, *invL;
    cudaGetSymbolAddress((void**)&Xh,   g_Xh);
    cudaGetSymbolAddress((void**)&Wc,   g_Wc);
    cudaGetSymbolAddress((void**)&QKVh, g_QKVh);
    cudaGetSymbolAddress((void**)&VTh,  g_VTh);
    cudaGetSymbolAddress((void**)&P,    g_P);
    cudaGetSymbolAddress((void**)&Part, g_Part);
    cudaGetSymbolAddress((void**)&invL, g_invL);

    cudaFuncSetAttribute((const void*)gemm_nt_h<0>,
                         cudaFuncAttributeMaxDynamicSharedMemorySize, SM_BYTES);
    cudaFuncSetAttribute((const void*)gemm_nt_h<1>,
                         cudaFuncAttributeMaxDynamicSharedMemorySize, SM_BYTES);
    cudaFuncSetAttribute((const void*)gemm_nt_h<2>,
                         cudaFuncAttributeMaxDynamicSharedMemorySize, SM_BYTES);

    dim3 blk(256);
    const float alpha = 1.0f / sqrtf((float)DIM);

    // (1) fp32 -> fp16 for x and packed weights
    constexpr int N4 = (SEQ * DIM + 3 * DIM * DIM) / 4;
    f2h_all<<<(N4 + 255) / 256, 256>>>(x, wq, wk, wv, Xh, Wc);

    // (2) fused projection: QKV = x @ Wc^T (q columns scaled by alpha), fp16 out
    dim3 gProj(QKV / BN, SEQ / BM);                  // 9 x 64
    gemm_nt_h<1><<<gProj, blk, SM_BYTES>>>(
        Xh, DIM, Wc, DIM, QKVh, QKV, alpha, DIM, DIM / BK, DIM / BK, 0);

    // (3) VT = transpose of V columns
    transpose_h<<<dim3(DIM / 32, SEQ / 32), 256>>>(QKVh + 2 * DIM, QKV, VTh);

    // (4) P = exp(Q @ K^T), unnormalized, fp16
    dim3 gScore(SEQ / BN, SEQ / BM);                 // 32 x 64
    gemm_nt_h<2><<<gScore, blk, SM_BYTES>>>(
        QKVh, QKV, QKVh + DIM, QKV, P, SEQ, 1.0f, 0, DIM / BK, DIM / BK, 0);

    // (5) invL[row] = 1 / sum_j P[row][j]
    rowsum_inv<<<SEQ, 256>>>(P, invL);

    // (6) PV split-K=3 partials: Part[z] = P[:, zK:...] @ V[zK:...]
    dim3 gPV(DIM / BN, SEQ / BM, 3);                 // 3 x 64 x 3
    gemm_nt_h<0><<<gPV, blk, SM_BYTES>>>(
        P, SEQ, VTh, SEQ, Part, DIM, 1.0f, 0, SEQ / BK, 43, (size_t)SEQ * DIM);

    // (7) out = (sum of partials) * invL[row]
    reduce_norm<<<(SEQ * DIM / 4 + 255) / 256, 256>>>(Part, out, invL);
}

// round 8
// speedup vs baseline: 1.1215x; 1.1215x over previous
#include <cuda_runtime.h>
#include <mma.h>
#include <cuda_fp16.h>
#include <cstdint>
#include <math.h>

using namespace nvcuda;

#define SEQ 8192
#define DIM 768
#define QKV (3 * DIM)   // 2304

// ---------------- scratch (static device arrays; no allocs) ----------------
__device__ __align__(128) __half g_Xh  [(size_t)SEQ * DIM];
__device__ __align__(128) __half g_Wc  [(size_t)QKV * DIM];       // packed wq|wk|wv
__device__ __align__(128) __half g_QKVh[(size_t)SEQ * QKV];       // [q | k | v] cols
__device__ __align__(128) __half g_VTh [(size_t)DIM * SEQ];
__device__ __align__(128) __half g_P   [(size_t)SEQ * SEQ];       // exp(s), unnormalized
__device__ __align__(128) float  g_RS  [(size_t)SEQ * 64];        // per-block row partials
__device__ __align__(128) float  g_Part[(size_t)3 * SEQ * DIM];   // PV split-K partials
__device__ __align__(128) float  g_invL[SEQ];

// ---------------- helpers ----------------
__device__ __forceinline__ uint32_t smem_u32(const void* p) {
    uint32_t a;
    asm("{ .reg .u64 t; cvta.to.shared.u64 t, %1; cvt.u32.u64 %0, t; }" : "=r"(a) : "l"(p));
    return a;
}
__device__ __forceinline__ void cp_async16(uint32_t dst, const void* src) {
    asm volatile("cp.async.cg.shared.global [%0], [%1], 16;" :: "r"(dst), "l"(src) : "memory");
}
#define CP_COMMIT() asm volatile("cp.async.commit_group;" ::: "memory")
#define CP_WAIT1()  asm volatile("cp.async.wait_group 1;" ::: "memory")
#define CP_WAIT0()  asm volatile("cp.async.wait_group 0;" ::: "memory")

// ---------------------------------------------------------------------------
// NT GEMM (fp16 in, fp32 acc): C[M,N] = a * A[M,K] @ B[N,K]^T
// BM=BN=128, BK=64. 128 threads = 4 warps (2x2), warp tile 64x64 (4x4 frags):
// 8 frag loads per 16 wmma. 3-stage cp.async. launch_bounds(128,2) -> no spill,
// 2 CTAs/SM. Split-K via blockIdx.z (EPI=0 only).
// EPI: 0 = fp32 direct store (+plane offset), 1 = fp16 smem-staged,
//      2 = fp16 staged with exp() + per-block row-sum partials into RS.
// ---------------------------------------------------------------------------
constexpr int BM = 128, BN = 128, BK = 64, LDSA = 72;   // 72 halves = 144B stride
constexpr int STG_A = BM * LDSA, STG_B = BN * LDSA;     // halves per stage
constexpr int SM_BYTES = 3 * (STG_A + STG_B) * 2;       // 110592

template <int EPI>
__global__ __launch_bounds__(128, 2) void gemm_nt_h(
    const __half* __restrict__ A, int lda,
    const __half* __restrict__ B, int ldb,
    void* __restrict__ Cv, int ldc,
    float alpha, int col_limit,
    int kTot, int splitIters, size_t planeStride,
    float* __restrict__ RS)
{
    extern __shared__ __half smh[];
    __half* As = smh;                   // 3 x STG_A
    __half* Bs = smh + 3 * STG_A;       // 3 x STG_B

    const int tid  = threadIdx.x;
    const int warp = tid >> 5;
    const int bm   = blockIdx.y * BM;
    const int bn   = blockIdx.x * BN;
    const int wm   = (warp & 1) * 64;
    const int wn   = (warp >> 1) * 64;

    const int z    = blockIdx.z;
    const int kit0 = z * splitIters;
    const int nit  = min(splitIters, kTot - kit0);

    const uint32_t sA = smem_u32(As);
    const uint32_t sB = smem_u32(Bs);

    auto load_tile = [&](int b, int it) {
        const int k0 = (kit0 + it) * BK;
        const uint32_t dA = sA + (uint32_t)(b * STG_A) * 2;
        #pragma unroll
        for (int t = 0; t < 8; t++) {                    // 1024 granules / 128 thr
            int g = tid + t * 128;
            int r = g >> 3, c = (g & 7) << 3;            // halves
            cp_async16(dA + (uint32_t)(r * LDSA + c) * 2,
                       A + (size_t)(bm + r) * lda + k0 + c);
        }
        const uint32_t dB = sB + (uint32_t)(b * STG_B) * 2;
        #pragma unroll
        for (int t = 0; t < 8; t++) {
            int g = tid + t * 128;
            int r = g >> 3, c = (g & 7) << 3;
            cp_async16(dB + (uint32_t)(r * LDSA + c) * 2,
                       B + (size_t)(bn + r) * ldb + k0 + c);
        }
        CP_COMMIT();
    };

    wmma::fragment<wmma::accumulator, 16, 16, 16, float> acc[4][4];
    #pragma unroll
    for (int mi = 0; mi < 4; mi++)
        #pragma unroll
        for (int ni = 0; ni < 4; ni++)
            wmma::fill_fragment(acc[mi][ni], 0.0f);

    load_tile(0, 0);
    load_tile(1, 1);

    for (int i = 0; i < nit; i++) {
        if (i + 1 < nit) { CP_WAIT1(); } else { CP_WAIT0(); }
        __syncthreads();
        if (i + 2 < nit) load_tile((i + 2) % 3, i + 2);

        const int s = i % 3;
        const __half* Ab = As + s * STG_A;
        const __half* Bb = Bs + s * STG_B;

        #pragma unroll
        for (int kk = 0; kk < BK; kk += 16) {
            wmma::fragment<wmma::matrix_a, 16, 16, 16, __half, wmma::row_major> af[4];
            wmma::fragment<wmma::matrix_b, 16, 16, 16, __half, wmma::col_major> bf[4];
            #pragma unroll
            for (int mi = 0; mi < 4; mi++)
                wmma::load_matrix_sync(af[mi], Ab + (wm + mi * 16) * LDSA + kk, LDSA);
            #pragma unroll
            for (int ni = 0; ni < 4; ni++)
                wmma::load_matrix_sync(bf[ni], Bb + (wn + ni * 16) * LDSA + kk, LDSA);
            #pragma unroll
            for (int mi = 0; mi < 4; mi++)
                #pragma unroll
                for (int ni = 0; ni < 4; ni++)
                    wmma::mma_sync(acc[mi][ni], af[mi], bf[ni], acc[mi][ni]);
        }
    }

    const float a = (bn < col_limit) ? alpha : 1.0f;

    if constexpr (EPI == 0) {
        float* C = (float*)Cv + (size_t)z * planeStride;
        #pragma unroll
        for (int mi = 0; mi < 4; mi++) {
            #pragma unroll
            for (int ni = 0; ni < 4; ni++) {
                #pragma unroll
                for (int e = 0; e < acc[mi][ni].num_elements; e++)
                    acc[mi][ni].x[e] *= a;
                wmma::store_matrix_sync(
                    C + (size_t)(bm + wm + mi * 16) * ldc + bn + wn + ni * 16,
                    acc[mi][ni], ldc, wmma::mem_row_major);
            }
        }
    } else {
        // stage fp32 tile in smem, convert to half (EPI=2: exp), coalesced store
        constexpr int LDC_S = 132;                       // floats
        float* Cs = (float*)smh;                         // 128*132*4 = 67584
        __half* Ps = (__half*)((char*)smh + 67584);      // 128*136*2 = 34816 (EPI=2)
        constexpr int LDP_S = 136;                       // halves
        __syncthreads();
        #pragma unroll
        for (int mi = 0; mi < 4; mi++) {
            #pragma unroll
            for (int ni = 0; ni < 4; ni++) {
                #pragma unroll
                for (int e = 0; e < acc[mi][ni].num_elements; e++)
                    acc[mi][ni].x[e] *= a;
                wmma::store_matrix_sync(Cs + (wm + mi * 16) * LDC_S + wn + ni * 16,
                                        acc[mi][ni], LDC_S, wmma::mem_row_major);
            }
        }
        __syncthreads();
        __half* C = (__half*)Cv;
        #pragma unroll
        for (int t = 0; t < 32; t++) {                   // 128x128 elems, 4/thread/iter
            int g = tid + t * 128;
            int r = g >> 5, c = (g & 31) << 2;
            float4 v = *reinterpret_cast<const float4*>(Cs + r * LDC_S + c);
            if constexpr (EPI == 2) {
                v.x = __expf(v.x); v.y = __expf(v.y);
                v.z = __expf(v.z); v.w = __expf(v.w);
            }
            __half2 h0 = __floats2half2_rn(v.x, v.y);
            __half2 h1 = __floats2half2_rn(v.z, v.w);
            uint2 u;
            u.x = *reinterpret_cast<uint32_t*>(&h0);
            u.y = *reinterpret_cast<uint32_t*>(&h1);
            *reinterpret_cast<uint2*>(C + (size_t)(bm + r) * ldc + bn + c) = u;
            if constexpr (EPI == 2)
                *reinterpret_cast<uint2*>(Ps + r * LDP_S + c) = u;
        }
        if constexpr (EPI == 2) {
            // deterministic per-block row sums of the exp'd (fp16-rounded) tile
            __syncthreads();
            const uint4* pr = reinterpret_cast<const uint4*>(Ps + tid * LDP_S);
            float s = 0.0f;
            #pragma unroll
            for (int j = 0; j < 16; j++) {               // 16 x 8 halves = 128
                uint4 q = pr[j];
                const __half2* h = reinterpret_cast<const __half2*>(&q);
                #pragma unroll
                for (int w = 0; w < 4; w++) {
                    float2 f = __half22float2(h[w]);
                    s += f.x + f.y;
                }
            }
            RS[(size_t)(bm + tid) * gridDim.x + blockIdx.x] = s;
        }
    }
}

// ---------------- fused fp32 -> fp16 conversion (x, wq, wk, wv) ----------------
__global__ void __launch_bounds__(256) f2h_all(
    const float* __restrict__ x,  const float* __restrict__ wq,
    const float* __restrict__ wk, const float* __restrict__ wv,
    __half* __restrict__ Xh, __half* __restrict__ Wc)
{
    constexpr int NX = SEQ * DIM / 4;
    constexpr int NW = DIM * DIM / 4;
    int i = blockIdx.x * 256 + threadIdx.x;
    const float* src; __half* dst; int j;
    if (i < NX)               { src = x;  dst = Xh;                 j = i; }
    else if (i < NX + NW)     { src = wq; dst = Wc;                 j = i - NX; }
    else if (i < NX + 2 * NW) { src = wk; dst = Wc + DIM * DIM;     j = i - NX - NW; }
    else if (i < NX + 3 * NW) { src = wv; dst = Wc + 2 * DIM * DIM; j = i - NX - 2 * NW; }
    else return;
    float4 v = reinterpret_cast<const float4*>(src)[j];
    __half2 h0 = __floats2half2_rn(v.x, v.y);
    __half2 h1 = __floats2half2_rn(v.z, v.w);
    uint2 u;
    u.x = *reinterpret_cast<uint32_t*>(&h0);
    u.y = *reinterpret_cast<uint32_t*>(&h1);
    reinterpret_cast<uint2*>(dst)[j] = u;
}

// ---------------- half transpose: in[SEQ][ld] (col slice) -> out[DIM][SEQ] ----------------
__global__ void __launch_bounds__(256) transpose_h(const __half* __restrict__ in, int ld,
                                                   __half* __restrict__ out)
{
    __shared__ __half t[32][34];
    const int x0 = blockIdx.x * 32;
    const int y0 = blockIdx.y * 32;
    const int tx = threadIdx.x & 31, ty = threadIdx.x >> 5;
    #pragma unroll
    for (int j = 0; j < 4; j++)
        t[ty + 8 * j][tx] = in[(size_t)(y0 + ty + 8 * j) * ld + x0 + tx];
    __syncthreads();
    #pragma unroll
    for (int j = 0; j < 4; j++)
        out[(size_t)(x0 + ty + 8 * j) * SEQ + y0 + tx] = t[tx][ty + 8 * j];
}

// ---------------- invL[row] = 1 / sum over 64 per-block partials ----------------
__global__ void __launch_bounds__(256) rowsum_inv(const float* __restrict__ RS,
                                                  float* __restrict__ invL)
{
    int row = blockIdx.x * 256 + threadIdx.x;
    if (row < SEQ) {
        const float4* p = reinterpret_cast<const float4*>(RS + (size_t)row * 64);
        float s = 0.0f;
        #pragma unroll
        for (int j = 0; j < 16; j++) {
            float4 v = p[j];
            s += v.x + v.y + v.z + v.w;
        }
        invL[row] = 1.0f / s;
    }
}

// ---------------- reduce split-K partials + row-normalize ----------------
__global__ void __launch_bounds__(256) reduce_norm(const float* __restrict__ part,
                                                   float* __restrict__ out,
                                                   const float* __restrict__ invL)
{
    constexpr int PLANE4 = SEQ * DIM / 4;
    int i = blockIdx.x * 256 + threadIdx.x;
    if (i < PLANE4) {
        const float s = invL[i / (DIM / 4)];
        const float4 a = reinterpret_cast<const float4*>(part)[i];
        const float4 b = reinterpret_cast<const float4*>(part)[i + PLANE4];
        const float4 c = reinterpret_cast<const float4*>(part)[i + 2 * PLANE4];
        float4 v;
        v.x = (a.x + b.x + c.x) * s;
        v.y = (a.y + b.y + c.y) * s;
        v.z = (a.z + b.z + c.z) * s;
        v.w = (a.w + b.w + c.w) * s;
        reinterpret_cast<float4*>(out)[i] = v;
    }
}

// ---------------- launch ----------------
extern "C" void kernel_launch(void* const* d_in, const int* in_sizes, int n_in,
                              void* d_out, int out_size)
{
    const float* x  = (const float*)d_in[0];
    const float* wq = (const float*)d_in[1];
    const float* wk = (const float*)d_in[2];
    const float* wv = (const float*)d_in[3];
    float* out = (float*)d_out;

    __half *Xh, *Wc, *QKVh, *VTh, *P;
    float *RS, *Part, *invL;
    cudaGetSymbolAddress((void**)&Xh,   g_Xh);
    cudaGetSymbolAddress((void**)&Wc,   g_Wc);
    cudaGetSymbolAddress((void**)&QKVh, g_QKVh);
    cudaGetSymbolAddress((void**)&VTh,  g_VTh);
    cudaGetSymbolAddress((void**)&P,    g_P);
    cudaGetSymbolAddress((void**)&RS,   g_RS);
    cudaGetSymbolAddress((void**)&Part, g_Part);
    cudaGetSymbolAddress((void**)&invL, g_invL);

    cudaFuncSetAttribute((const void*)gemm_nt_h<0>,
                         cudaFuncAttributeMaxDynamicSharedMemorySize, SM_BYTES);
    cudaFuncSetAttribute((const void*)gemm_nt_h<1>,
                         cudaFuncAttributeMaxDynamicSharedMemorySize, SM_BYTES);
    cudaFuncSetAttribute((const void*)gemm_nt_h<2>,
                         cudaFuncAttributeMaxDynamicSharedMemorySize, SM_BYTES);

    dim3 blk(128);
    const float alpha = 1.0f / sqrtf((float)DIM);

    // (1) fp32 -> fp16 for x and packed weights
    constexpr int N4 = (SEQ * DIM + 3 * DIM * DIM) / 4;
    f2h_all<<<(N4 + 255) / 256, 256>>>(x, wq, wk, wv, Xh, Wc);

    // (2) fused projection: QKV = x @ Wc^T (q columns scaled by alpha), fp16 out
    dim3 gProj(QKV / BN, SEQ / BM);                  // 18 x 64
    gemm_nt_h<1><<<gProj, blk, SM_BYTES>>>(
        Xh, DIM, Wc, DIM, QKVh, QKV, alpha, DIM, DIM / BK, DIM / BK, 0, nullptr);

    // (3) VT = transpose of V columns
    transpose_h<<<dim3(DIM / 32, SEQ / 32), 256>>>(QKVh + 2 * DIM, QKV, VTh);

    // (4) P = exp(Q @ K^T), fp16, + per-block row-sum partials into RS
    dim3 gScore(SEQ / BN, SEQ / BM);                 // 64 x 64
    gemm_nt_h<2><<<gScore, blk, SM_BYTES>>>(
        QKVh, QKV, QKVh + DIM, QKV, P, SEQ, 1.0f, 0, DIM / BK, DIM / BK, 0, RS);

    // (5) invL[row] = 1 / sum of partials
    rowsum_inv<<<SEQ / 256, 256>>>(RS, invL);

    // (6) PV split-K=3 partials
    dim3 gPV(DIM / BN, SEQ / BM, 3);                 // 6 x 64 x 3
    gemm_nt_h<0><<<gPV, blk, SM_BYTES>>>(
        P, SEQ, VTh, SEQ, Part, DIM, 1.0f, 0, SEQ / BK, 43, (size_t)SEQ * DIM, nullptr);

    // (7) out = (sum of partials) * invL[row]
    reduce_norm<<<(SEQ * DIM / 4 + 255) / 256, 256>>>(Part, out, invL);
}

// round 9
// speedup vs baseline: 1.1225x; 1.0009x over previous
#include <cuda_runtime.h>
#include <mma.h>
#include <cuda_fp16.h>
#include <cstdint>
#include <math.h>

using namespace nvcuda;

#define SEQ 8192
#define DIM 768
#define QKV (3 * DIM)   // 2304

// ---------------- scratch (static device arrays; no allocs) ----------------
__device__ __align__(128) __half g_Xh  [(size_t)SEQ * DIM];
__device__ __align__(128) __half g_Wc  [(size_t)QKV * DIM];       // packed wq|wk|wv
__device__ __align__(128) __half g_QKVh[(size_t)SEQ * QKV];       // [q | k | v] cols
__device__ __align__(128) __half g_P   [(size_t)SEQ * SEQ];       // exp(s), unnormalized
__device__ __align__(128) float  g_RS  [(size_t)SEQ * 64];        // per-block row partials
__device__ __align__(128) float  g_Part[(size_t)3 * SEQ * DIM];   // PV split-K partials
__device__ __align__(128) float  g_invL[SEQ];

// ---------------- helpers ----------------
__device__ __forceinline__ uint32_t smem_u32(const void* p) {
    uint32_t a;
    asm("{ .reg .u64 t; cvta.to.shared.u64 t, %1; cvt.u32.u64 %0, t; }" : "=r"(a) : "l"(p));
    return a;
}
__device__ __forceinline__ void cp_async16(uint32_t dst, const void* src) {
    asm volatile("cp.async.cg.shared.global [%0], [%1], 16;" :: "r"(dst), "l"(src) : "memory");
}
#define CP_COMMIT() asm volatile("cp.async.commit_group;" ::: "memory")
#define CP_WAIT1()  asm volatile("cp.async.wait_group 1;" ::: "memory")
#define CP_WAIT0()  asm volatile("cp.async.wait_group 0;" ::: "memory")

// ---------------------------------------------------------------------------
// GEMM (fp16 in, fp32 acc), BM=BN=128, BK=64, 256 thr = 8 warps (2x2m x 4n),
// warp tile 64x32 (4x2 frags). 3-stage cp.async, launch_bounds(256,2).
//   BT=true  (NT): C = a * A[M,K] @ B[N,K]^T   (B K-contiguous)
//   BT=false (NN): C = a * A[M,K] @ B[K,N]     (B N-contiguous)
// Split-K via blockIdx.z (EPI=0 only; plane offset z*planeStride).
// EPI: 0 = fp32 direct store, 1 = fp16 smem-staged store,
//      2 = fp16 staged with exp() + per-block row sums into RS.
// ---------------------------------------------------------------------------
constexpr int BM = 128, BN = 128, BK = 64;
constexpr int LDA = 72;                       // A smem stride (halves)
constexpr int STG_A = BM * LDA;

template <int EPI, bool BT>
__global__ __launch_bounds__(256, 2) void gemm_h(
    const __half* __restrict__ A, int lda,
    const __half* __restrict__ B, int ldb,
    void* __restrict__ Cv, int ldc,
    float alpha, int col_limit,
    int kTot, int splitIters, size_t planeStride,
    float* __restrict__ RS)
{
    constexpr int LDB   = BT ? 72 : 136;      // halves
    constexpr int STG_B = BT ? BN * 72 : BK * 136;

    extern __shared__ __half smh[];
    __half* As = smh;                         // 3 x STG_A
    __half* Bs = smh + 3 * STG_A;             // 3 x STG_B

    const int tid  = threadIdx.x;
    const int warp = tid >> 5;
    const int bm   = blockIdx.y * BM;
    const int bn   = blockIdx.x * BN;
    const int wm   = (warp & 1) * 64;
    const int wn   = (warp >> 1) * 32;

    const int z    = blockIdx.z;
    const int kit0 = z * splitIters;
    const int nit  = min(splitIters, kTot - kit0);

    const uint32_t sA = smem_u32(As);
    const uint32_t sB = smem_u32(Bs);

    auto load_tile = [&](int b, int it) {
        const int k0 = (kit0 + it) * BK;
        const uint32_t dA = sA + (uint32_t)(b * STG_A) * 2;
        #pragma unroll
        for (int t = 0; t < 4; t++) {                    // A: 1024 granules
            int g = tid + t * 256;
            int r = g >> 3, c = (g & 7) << 3;            // halves
            cp_async16(dA + (uint32_t)(r * LDA + c) * 2,
                       A + (size_t)(bm + r) * lda + k0 + c);
        }
        const uint32_t dB = sB + (uint32_t)(b * STG_B) * 2;
        if constexpr (BT) {
            #pragma unroll
            for (int t = 0; t < 4; t++) {                // B[N,K]: 1024 granules
                int g = tid + t * 256;
                int r = g >> 3, c = (g & 7) << 3;
                cp_async16(dB + (uint32_t)(r * LDB + c) * 2,
                           B + (size_t)(bn + r) * ldb + k0 + c);
            }
        } else {
            #pragma unroll
            for (int t = 0; t < 4; t++) {                // B[K,N]: 64 rows x 16 granules
                int g = tid + t * 256;
                int r = g >> 4, c = (g & 15) << 3;
                cp_async16(dB + (uint32_t)(r * LDB + c) * 2,
                           B + (size_t)(k0 + r) * ldb + bn + c);
            }
        }
        CP_COMMIT();
    };

    wmma::fragment<wmma::accumulator, 16, 16, 16, float> acc[4][2];
    #pragma unroll
    for (int mi = 0; mi < 4; mi++)
        #pragma unroll
        for (int ni = 0; ni < 2; ni++)
            wmma::fill_fragment(acc[mi][ni], 0.0f);

    load_tile(0, 0);
    load_tile(1, 1);

    #pragma unroll 3
    for (int i = 0; i < nit; i++) {
        if (i + 1 < nit) { CP_WAIT1(); } else { CP_WAIT0(); }
        __syncthreads();
        if (i + 2 < nit) load_tile((i + 2) % 3, i + 2);

        const int s = i % 3;
        const __half* Ab = As + s * STG_A;
        const __half* Bb = Bs + s * STG_B;

        #pragma unroll
        for (int kk = 0; kk < BK; kk += 16) {
            wmma::fragment<wmma::matrix_a, 16, 16, 16, __half, wmma::row_major> af[4];
            #pragma unroll
            for (int mi = 0; mi < 4; mi++)
                wmma::load_matrix_sync(af[mi], Ab + (wm + mi * 16) * LDA + kk, LDA);

            if constexpr (BT) {
                wmma::fragment<wmma::matrix_b, 16, 16, 16, __half, wmma::col_major> bf[2];
                #pragma unroll
                for (int ni = 0; ni < 2; ni++)
                    wmma::load_matrix_sync(bf[ni], Bb + (wn + ni * 16) * LDB + kk, LDB);
                #pragma unroll
                for (int mi = 0; mi < 4; mi++)
                    #pragma unroll
                    for (int ni = 0; ni < 2; ni++)
                        wmma::mma_sync(acc[mi][ni], af[mi], bf[ni], acc[mi][ni]);
            } else {
                wmma::fragment<wmma::matrix_b, 16, 16, 16, __half, wmma::row_major> bf[2];
                #pragma unroll
                for (int ni = 0; ni < 2; ni++)
                    wmma::load_matrix_sync(bf[ni], Bb + kk * LDB + wn + ni * 16, LDB);
                #pragma unroll
                for (int mi = 0; mi < 4; mi++)
                    #pragma unroll
                    for (int ni = 0; ni < 2; ni++)
                        wmma::mma_sync(acc[mi][ni], af[mi], bf[ni], acc[mi][ni]);
            }
        }
    }

    const float a = (bn < col_limit) ? alpha : 1.0f;

    if constexpr (EPI == 0) {
        float* C = (float*)Cv + (size_t)z * planeStride;
        #pragma unroll
        for (int mi = 0; mi < 4; mi++) {
            #pragma unroll
            for (int ni = 0; ni < 2; ni++) {
                #pragma unroll
                for (int e = 0; e < acc[mi][ni].num_elements; e++)
                    acc[mi][ni].x[e] *= a;
                wmma::store_matrix_sync(
                    C + (size_t)(bm + wm + mi * 16) * ldc + bn + wn + ni * 16,
                    acc[mi][ni], ldc, wmma::mem_row_major);
            }
        }
    } else {
        // stage fp32 tile in smem; convert (EPI=2: exp) to fp16; coalesced store
        constexpr int LDC_S = 132;                       // floats
        float* Cs = (float*)smh;                         // 128*132*4 = 67584
        __syncthreads();
        #pragma unroll
        for (int mi = 0; mi < 4; mi++) {
            #pragma unroll
            for (int ni = 0; ni < 2; ni++) {
                #pragma unroll
                for (int e = 0; e < acc[mi][ni].num_elements; e++)
                    acc[mi][ni].x[e] *= a;
                wmma::store_matrix_sync(Cs + (wm + mi * 16) * LDC_S + wn + ni * 16,
                                        acc[mi][ni], LDC_S, wmma::mem_row_major);
            }
        }
        __syncthreads();
        __half* C = (__half*)Cv;
        #pragma unroll
        for (int t = 0; t < 16; t++) {                   // 128x128 elems, 4/thread/iter
            int g = tid + t * 256;
            int r = g >> 5, c = (g & 31) << 2;
            float4 v = *reinterpret_cast<const float4*>(Cs + r * LDC_S + c);
            if constexpr (EPI == 2) {
                v.x = __expf(v.x); v.y = __expf(v.y);
                v.z = __expf(v.z); v.w = __expf(v.w);
                *reinterpret_cast<float4*>(Cs + r * LDC_S + c) = v;   // for rowsum
            }
            __half2 h0 = __floats2half2_rn(v.x, v.y);
            __half2 h1 = __floats2half2_rn(v.z, v.w);
            uint2 u;
            u.x = *reinterpret_cast<uint32_t*>(&h0);
            u.y = *reinterpret_cast<uint32_t*>(&h1);
            *reinterpret_cast<uint2*>(C + (size_t)(bm + r) * ldc + bn + c) = u;
        }
        if constexpr (EPI == 2) {
            __syncthreads();
            if (tid < 128) {                             // per-block row sums
                const float4* pr = reinterpret_cast<const float4*>(Cs + tid * LDC_S);
                float s = 0.0f;
                #pragma unroll
                for (int j = 0; j < 32; j++) {
                    float4 v = pr[j];
                    s += v.x + v.y + v.z + v.w;
                }
                RS[(size_t)(bm + tid) * gridDim.x + blockIdx.x] = s;
            }
        }
    }
}

// ---------------- fused fp32 -> fp16 conversion (x, wq, wk, wv) ----------------
__global__ void __launch_bounds__(256) f2h_all(
    const float* __restrict__ x,  const float* __restrict__ wq,
    const float* __restrict__ wk, const float* __restrict__ wv,
    __half* __restrict__ Xh, __half* __restrict__ Wc)
{
    constexpr int NX = SEQ * DIM / 4;
    constexpr int NW = DIM * DIM / 4;
    int i = blockIdx.x * 256 + threadIdx.x;
    const float* src; __half* dst; int j;
    if (i < NX)               { src = x;  dst = Xh;                 j = i; }
    else if (i < NX + NW)     { src = wq; dst = Wc;                 j = i - NX; }
    else if (i < NX + 2 * NW) { src = wk; dst = Wc + DIM * DIM;     j = i - NX - NW; }
    else if (i < NX + 3 * NW) { src = wv; dst = Wc + 2 * DIM * DIM; j = i - NX - 2 * NW; }
    else return;
    float4 v = reinterpret_cast<const float4*>(src)[j];
    __half2 h0 = __floats2half2_rn(v.x, v.y);
    __half2 h1 = __floats2half2_rn(v.z, v.w);
    uint2 u;
    u.x = *reinterpret_cast<uint32_t*>(&h0);
    u.y = *reinterpret_cast<uint32_t*>(&h1);
    reinterpret_cast<uint2*>(dst)[j] = u;
}

// ---------------- invL[row] = 1 / sum over 64 per-block partials ----------------
__global__ void __launch_bounds__(256) rowsum_inv(const float* __restrict__ RS,
                                                  float* __restrict__ invL)
{
    int row = blockIdx.x * 256 + threadIdx.x;
    if (row < SEQ) {
        const float4* p = reinterpret_cast<const float4*>(RS + (size_t)row * 64);
        float s = 0.0f;
        #pragma unroll
        for (int j = 0; j < 16; j++) {
            float4 v = p[j];
            s += v.x + v.y + v.z + v.w;
        }
        invL[row] = 1.0f / s;
    }
}

// ---------------- reduce split-K partials + row-normalize ----------------
__global__ void __launch_bounds__(256) reduce_norm(const float* __restrict__ part,
                                                   float* __restrict__ out,
                                                   const float* __restrict__ invL)
{
    constexpr int PLANE4 = SEQ * DIM / 4;
    int i = blockIdx.x * 256 + threadIdx.x;
    if (i < PLANE4) {
        const float s = invL[i / (DIM / 4)];
        const float4 a = reinterpret_cast<const float4*>(part)[i];
        const float4 b = reinterpret_cast<const float4*>(part)[i + PLANE4];
        const float4 c = reinterpret_cast<const float4*>(part)[i + 2 * PLANE4];
        float4 v;
        v.x = (a.x + b.x + c.x) * s;
        v.y = (a.y + b.y + c.y) * s;
        v.z = (a.z + b.z + c.z) * s;
        v.w = (a.w + b.w + c.w) * s;
        reinterpret_cast<float4*>(out)[i] = v;
    }
}

// ---------------- launch ----------------
extern "C" void kernel_launch(void* const* d_in, const int* in_sizes, int n_in,
                              void* d_out, int out_size)
{
    const float* x  = (const float*)d_in[0];
    const float* wq = (const float*)d_in[1];
    const float* wk = (const float*)d_in[2];
    const float* wv = (const float*)d_in[3];
    float* out = (float*)d_out;

    __half *Xh, *Wc, *QKVh, *P;
    float *RS, *Part, *invL;
    cudaGetSymbolAddress((void**)&Xh,   g_Xh);
    cudaGetSymbolAddress((void**)&Wc,   g_Wc);
    cudaGetSymbolAddress((void**)&QKVh, g_QKVh);
    cudaGetSymbolAddress((void**)&P,    g_P);
    cudaGetSymbolAddress((void**)&RS,   g_RS);
    cudaGetSymbolAddress((void**)&Part, g_Part);
    cudaGetSymbolAddress((void**)&invL, g_invL);

    constexpr int SM_NT = 3 * (STG_A + BN * 72) * 2;    // 110592
    constexpr int SM_NN = 3 * (STG_A + BK * 136) * 2;   // 107520
    cudaFuncSetAttribute((const void*)gemm_h<1, true>,
                         cudaFuncAttributeMaxDynamicSharedMemorySize, SM_NT);
    cudaFuncSetAttribute((const void*)gemm_h<2, true>,
                         cudaFuncAttributeMaxDynamicSharedMemorySize, SM_NT);
    cudaFuncSetAttribute((const void*)gemm_h<0, false>,
                         cudaFuncAttributeMaxDynamicSharedMemorySize, SM_NN);

    dim3 blk(256);
    const float alpha = 1.0f / sqrtf((float)DIM);

    // (1) fp32 -> fp16 for x and packed weights
    constexpr int N4 = (SEQ * DIM + 3 * DIM * DIM) / 4;
    f2h_all<<<(N4 + 255) / 256, 256>>>(x, wq, wk, wv, Xh, Wc);

    // (2) fused projection (NT): QKV = x @ Wc^T (q cols scaled by alpha), fp16
    dim3 gProj(QKV / BN, SEQ / BM);                  // 18 x 64
    gemm_h<1, true><<<gProj, blk, SM_NT>>>(
        Xh, DIM, Wc, DIM, QKVh, QKV, alpha, DIM, DIM / BK, DIM / BK, 0, nullptr);

    // (3) P = exp(Q @ K^T) (NT), fp16, + per-block row-sum partials
    dim3 gScore(SEQ / BN, SEQ / BM);                 // 64 x 64
    gemm_h<2, true><<<gScore, blk, SM_NT>>>(
        QKVh, QKV, QKVh + DIM, QKV, P, SEQ, 1.0f, 0, DIM / BK, DIM / BK, 0, RS);

    // (4) invL[row] = 1 / sum of partials
    rowsum_inv<<<SEQ / 256, 256>>>(RS, invL);

    // (5) PV (NN, B = V slice of QKVh) split-K=3 partials
    dim3 gPV(DIM / BN, SEQ / BM, 3);                 // 6 x 64 x 3
    gemm_h<0, false><<<gPV, blk, SM_NN>>>(
        P, SEQ, QKVh + 2 * DIM, QKV, Part, DIM, 1.0f, 0, SEQ / BK, 43,
        (size_t)SEQ * DIM, nullptr);

    // (6) out = (sum of partials) * invL[row]
    reduce_norm<<<(SEQ * DIM / 4 + 255) / 256, 256>>>(Part, out, invL);
}